// round 9
// baseline (speedup 1.0000x reference)
#include <cuda_runtime.h>
#include <cuda_fp16.h>
#include <math.h>
#include <stdint.h>

#define N_NODES 50000
#define N_EDGES 1600000
#define E_TOT   (N_EDGES + N_NODES)
#define HID     128
#define SLOPE   0.2f

// ------------------------- device scratch (no allocs allowed) ---------------
__device__ __half g_XLh[(size_t)N_NODES * HID];
__device__ __half g_XRh[(size_t)N_NODES * HID];
__device__ float  g_H1[(size_t)N_NODES * HID];
__device__ int    g_DEG[N_NODES];       // zero-init; fused scan re-zeroes
__device__ int    g_ROWPTR[N_NODES + 1];
__device__ int    g_CURSOR[N_NODES];
__device__ int    g_CSR[E_TOT];
__device__ int    g_PART[64];           // zeroed by k_hist block 0 each pass

// ------------------------- edge dtype helpers --------------------------------
__device__ __forceinline__ int detect_is64(const void* e) {
    int flag = (((const int*)e)[2 * threadIdx.x + 1] != 0);
    return !__syncthreads_or(flag);
}

// load 4 consecutive values from the edge array starting at idx (idx % 4 == 0)
__device__ __forceinline__ int4 edge_val4(const void* e, int is64, int idx) {
    if (is64) {
        const int4* p = (const int4*)((const long long*)e + idx);
        int4 a = __ldg(p);          // two int64: (lo,hi,lo,hi)
        int4 b = __ldg(p + 1);
        return make_int4(a.x, a.z, b.x, b.z);
    } else {
        return __ldg((const int4*)((const int*)e + idx));
    }
}

// ------------------------- CSR build (4 edges / thread) ----------------------
__global__ __launch_bounds__(256) void k_hist(const void* __restrict__ e) {
    if (blockIdx.x == 0 && threadIdx.x < 64) g_PART[threadIdx.x] = 0;
    int is64 = detect_is64(e);
    int base = (blockIdx.x * 256 + threadIdx.x) * 4;
    if (base >= E_TOT) return;
    if (base < N_EDGES) {                   // N_EDGES % 4 == 0: fully inside
        int4 d = edge_val4(e, is64, N_EDGES + base);
        atomicAdd(&g_DEG[d.x], 1);
        atomicAdd(&g_DEG[d.y], 1);
        atomicAdd(&g_DEG[d.z], 1);
        atomicAdd(&g_DEG[d.w], 1);
    } else {                                // self-loop region: dst = i - N_EDGES
        int n = base - N_EDGES;
        atomicAdd(&g_DEG[n], 1);
        atomicAdd(&g_DEG[n + 1], 1);
        atomicAdd(&g_DEG[n + 2], 1);
        atomicAdd(&g_DEG[n + 3], 1);
    }
}

// fused scan: block-local scan + decoupled lookback over block partials.
__global__ __launch_bounds__(1024) void k_scanf() {
    __shared__ int s[1024];
    __shared__ int off_s;
    int i = blockIdx.x * 1024 + threadIdx.x;
    int v = (i < N_NODES) ? g_DEG[i] : 0;
    if (i < N_NODES) g_DEG[i] = 0;          // reset for next launch sequence
    s[threadIdx.x] = v;
    __syncthreads();
    #pragma unroll
    for (int off = 1; off < 1024; off <<= 1) {
        int t = (threadIdx.x >= off) ? s[threadIdx.x - off] : 0;
        __syncthreads();
        s[threadIdx.x] += t;
        __syncthreads();
    }
    int incl = s[threadIdx.x];
    if (threadIdx.x == 1023)
        atomicExch(&g_PART[blockIdx.x], incl);
    if (threadIdx.x < 32) {
        int sum = 0;
        for (int b = threadIdx.x; b < (int)blockIdx.x; b += 32) {
            int t;
            do { t = atomicAdd(&g_PART[b], 0); } while (t == 0);
            sum += t;
        }
        #pragma unroll
        for (int d = 16; d > 0; d >>= 1)
            sum += __shfl_down_sync(0xFFFFFFFFu, sum, d);
        if (threadIdx.x == 0) off_s = sum;
    }
    __syncthreads();
    if (i < N_NODES) {
        int r = incl - v + off_s;
        g_ROWPTR[i] = r;
        g_CURSOR[i] = r;
    }
    if (i == 0) g_ROWPTR[N_NODES] = E_TOT;
}

__global__ __launch_bounds__(256) void k_scatter(const void* __restrict__ e) {
    int is64 = detect_is64(e);
    int base = (blockIdx.x * 256 + threadIdx.x) * 4;
    if (base >= E_TOT) return;
    int4 sv, dv;
    if (base < N_EDGES) {
        sv = edge_val4(e, is64, base);
        dv = edge_val4(e, is64, N_EDGES + base);
    } else {
        int n = base - N_EDGES;
        sv = make_int4(n, n + 1, n + 2, n + 3);
        dv = sv;
    }
    int p0 = atomicAdd(&g_CURSOR[dv.x], 1);
    int p1 = atomicAdd(&g_CURSOR[dv.y], 1);
    int p2 = atomicAdd(&g_CURSOR[dv.z], 1);
    int p3 = atomicAdd(&g_CURSOR[dv.w], 1);
    g_CSR[p0] = sv.x;
    g_CSR[p1] = sv.y;
    g_CSR[p2] = sv.z;
    g_CSR[p3] = sv.w;
}

// ------------------------- fp16 tensor-core dual GEMM ------------------------
#define ASP_STRIDE 20
#define WSP_STRIDE 260

__device__ __forceinline__ void mma_f16(float4& d, const unsigned a[4], const unsigned b[2]) {
    asm volatile(
        "mma.sync.aligned.m16n8k16.row.col.f32.f16.f16.f32 "
        "{%0,%1,%2,%3}, {%4,%5,%6,%7}, {%8,%9}, {%0,%1,%2,%3};"
        : "+f"(d.x), "+f"(d.y), "+f"(d.z), "+f"(d.w)
        : "r"(a[0]), "r"(a[1]), "r"(a[2]), "r"(a[3]), "r"(b[0]), "r"(b[1]));
}

__global__ __launch_bounds__(512, 1) void k_gemm_tc(const float* __restrict__ A,
                                                    const float* __restrict__ Wl,
                                                    const float* __restrict__ Wr,
                                                    __half* __restrict__ XL,
                                                    __half* __restrict__ XR, int M) {
    __shared__ __half2 Asp[128][ASP_STRIDE];
    __shared__ __half2 Wsp[16][WSP_STRIDE];

    int tid = threadIdx.x;
    int wid = tid >> 5, lane = tid & 31;
    int g = lane >> 2, t = lane & 3;
    int wm = wid & 3, wn = wid >> 2;
    int m0 = blockIdx.x * 128;

    float4 C[2][8];
    #pragma unroll
    for (int i = 0; i < 2; i++)
        #pragma unroll
        for (int j = 0; j < 8; j++) C[i][j] = make_float4(0.f, 0.f, 0.f, 0.f);

    for (int k0 = 0; k0 < 128; k0 += 32) {
        #pragma unroll
        for (int j = 0; j < 2; j++) {
            int f = tid + 512 * j;
            int row = f >> 3, colf = (f & 7) * 4;
            float4 v = make_float4(0.f, 0.f, 0.f, 0.f);
            if (m0 + row < M)
                v = *(const float4*)(A + (size_t)(m0 + row) * 128 + k0 + colf);
            int c2 = colf >> 1;
            Asp[row][c2]     = __floats2half2_rn(v.x, v.y);
            Asp[row][c2 + 1] = __floats2half2_rn(v.z, v.w);
        }
        #pragma unroll
        for (int j = 0; j < 2; j++) {
            int f = tid + 512 * j;
            int k2 = f >> 6, nf = (f & 63) * 4;
            int k = k0 + 2 * k2;
            const float* W0 = (nf < 128) ? (Wl + (size_t)k * 128 + nf)
                                         : (Wr + (size_t)k * 128 + (nf - 128));
            const float* W1 = W0 + 128;
            float4 v0 = *(const float4*)W0;
            float4 v1 = *(const float4*)W1;
            Wsp[k2][nf]     = __floats2half2_rn(v0.x, v1.x);
            Wsp[k2][nf + 1] = __floats2half2_rn(v0.y, v1.y);
            Wsp[k2][nf + 2] = __floats2half2_rn(v0.z, v1.z);
            Wsp[k2][nf + 3] = __floats2half2_rn(v0.w, v1.w);
        }
        __syncthreads();

        #pragma unroll
        for (int ks2 = 0; ks2 < 16; ks2 += 8) {
            unsigned a[2][4], b[8][2];
            #pragma unroll
            for (int mt = 0; mt < 2; mt++) {
                int r = wm * 32 + mt * 16;
                a[mt][0] = *(const unsigned*)&Asp[r + g][ks2 + t];
                a[mt][1] = *(const unsigned*)&Asp[r + g + 8][ks2 + t];
                a[mt][2] = *(const unsigned*)&Asp[r + g][ks2 + t + 4];
                a[mt][3] = *(const unsigned*)&Asp[r + g + 8][ks2 + t + 4];
            }
            #pragma unroll
            for (int j = 0; j < 8; j++) {
                int n = wn * 64 + j * 8 + g;
                b[j][0] = *(const unsigned*)&Wsp[ks2 + t][n];
                b[j][1] = *(const unsigned*)&Wsp[ks2 + t + 4][n];
            }
            #pragma unroll
            for (int mt = 0; mt < 2; mt++)
                #pragma unroll
                for (int j = 0; j < 8; j++) mma_f16(C[mt][j], a[mt], b[j]);
        }
        __syncthreads();
    }

    __half* base = (wn < 2) ? XL : XR;
    int ncol0 = (wn & 1) * 64;
    #pragma unroll
    for (int mt = 0; mt < 2; mt++) {
        int r0 = m0 + wm * 32 + mt * 16 + g;
        #pragma unroll
        for (int j = 0; j < 8; j++) {
            int c = ncol0 + j * 8 + 2 * t;
            if (r0 < M)
                *(__half2*)(base + (size_t)r0 * 128 + c) = __floats2half2_rn(C[mt][j].x, C[mt][j].y);
            if (r0 + 8 < M)
                *(__half2*)(base + (size_t)(r0 + 8) * 128 + c) = __floats2half2_rn(C[mt][j].z, C[mt][j].w);
        }
    }
}

// ------------------------- GATv2 aggregation ---------------------------------
// Warp per dst node, two edges in flight per half-warp, fp16 gathers,
// software-pipelined mainloop (next CSR indices + rows issued before the
// current iteration's compute).
__device__ __forceinline__ void unp16(uint4 u, float4& A, float4& B) {
    float2 f0 = __half22float2(*reinterpret_cast<__half2*>(&u.x));
    float2 f1 = __half22float2(*reinterpret_cast<__half2*>(&u.y));
    float2 f2 = __half22float2(*reinterpret_cast<__half2*>(&u.z));
    float2 f3 = __half22float2(*reinterpret_cast<__half2*>(&u.w));
    A = make_float4(f0.x, f0.y, f1.x, f1.y);
    B = make_float4(f2.x, f2.y, f3.x, f3.y);
}

__device__ __forceinline__ float logit8(const float4& xA, const float4& xB,
                                        const float4& xrA, const float4& xrB,
                                        const float4& a6A, const float4& a4A,
                                        const float4& a6B, const float4& a4B) {
    float vx = xA.x + xrA.x, vy = xA.y + xrA.y, vz = xA.z + xrA.z, vw = xA.w + xrA.w;
    float p = a6A.x * vx + a4A.x * fabsf(vx);
    p = fmaf(a6A.y, vy, fmaf(a4A.y, fabsf(vy), p));
    p = fmaf(a6A.z, vz, fmaf(a4A.z, fabsf(vz), p));
    p = fmaf(a6A.w, vw, fmaf(a4A.w, fabsf(vw), p));
    vx = xB.x + xrB.x; vy = xB.y + xrB.y; vz = xB.z + xrB.z; vw = xB.w + xrB.w;
    p = fmaf(a6B.x, vx, fmaf(a4B.x, fabsf(vx), p));
    p = fmaf(a6B.y, vy, fmaf(a4B.y, fabsf(vy), p));
    p = fmaf(a6B.z, vz, fmaf(a4B.z, fabsf(vz), p));
    p = fmaf(a6B.w, vw, fmaf(a4B.w, fabsf(vw), p));
    return p;
}

// accumulate one 4-edge group held in (u0, u1)
#define AGG_STEP(u0, u1)                                                     \
    do {                                                                     \
        float4 x0A, x0B, x1A, x1B;                                           \
        unp16(u0, x0A, x0B);                                                 \
        unp16(u1, x1A, x1B);                                                 \
        float p0 = logit8(x0A, x0B, xrA, xrB, a6A, a4A, a6B, a4B);           \
        float p1 = logit8(x1A, x1B, xrA, xrB, a6A, a4A, a6B, a4B);           \
        p0 += __shfl_xor_sync(0xFFFFFFFFu, p0, 1);                           \
        p1 += __shfl_xor_sync(0xFFFFFFFFu, p1, 1);                           \
        p0 += __shfl_xor_sync(0xFFFFFFFFu, p0, 2);                           \
        p1 += __shfl_xor_sync(0xFFFFFFFFu, p1, 2);                           \
        float w0 = __expf(p0), w1 = __expf(p1);                              \
        s += w0 + w1;                                                        \
        accA.x += w0 * x0A.x + w1 * x1A.x;                                   \
        accA.y += w0 * x0A.y + w1 * x1A.y;                                   \
        accA.z += w0 * x0A.z + w1 * x1A.z;                                   \
        accA.w += w0 * x0A.w + w1 * x1A.w;                                   \
        accB.x += w0 * x0B.x + w1 * x1B.x;                                   \
        accB.y += w0 * x0B.y + w1 * x1B.y;                                   \
        accB.z += w0 * x0B.z + w1 * x1B.z;                                   \
        accB.w += w0 * x0B.w + w1 * x1B.w;                                   \
    } while (0)

__global__ __launch_bounds__(256) void k_agg(const __half* __restrict__ XL,
                                             const __half* __restrict__ XR,
                                             const float* __restrict__ att,
                                             const float* __restrict__ bias,
                                             float* __restrict__ out) {
    int warp = (blockIdx.x * blockDim.x + threadIdx.x) >> 5;
    int lane = threadIdx.x & 31;
    if (warp >= N_NODES) return;
    int half = lane >> 4;
    int hl   = lane & 15;

    const float4* attp = (const float4*)att;
    float4 aA = __ldg(attp + 2 * hl), aB = __ldg(attp + 2 * hl + 1);
    float4 a6A = make_float4(0.6f * aA.x, 0.6f * aA.y, 0.6f * aA.z, 0.6f * aA.w);
    float4 a4A = make_float4(0.4f * aA.x, 0.4f * aA.y, 0.4f * aA.z, 0.4f * aA.w);
    float4 a6B = make_float4(0.6f * aB.x, 0.6f * aB.y, 0.6f * aB.z, 0.6f * aB.w);
    float4 a4B = make_float4(0.4f * aB.x, 0.4f * aB.y, 0.4f * aB.z, 0.4f * aB.w);

    uint4 xru = __ldg((const uint4*)(XR + (size_t)warp * 128) + hl);
    float4 xrA, xrB;
    unp16(xru, xrA, xrB);

    int e0 = __ldg(&g_ROWPTR[warp]);
    int e1 = __ldg(&g_ROWPTR[warp + 1]);

    float s = 0.f;
    float4 accA = make_float4(0.f, 0.f, 0.f, 0.f);
    float4 accB = make_float4(0.f, 0.f, 0.f, 0.f);

    int e = e0;
    int nfull = (e1 - e0) >> 2;
    if (nfull > 0) {
        // stage 0
        int s0 = __ldg(&g_CSR[e + half]);
        int s1 = __ldg(&g_CSR[e + 2 + half]);
        uint4 u0 = __ldg((const uint4*)(XL + (size_t)s0 * 128) + hl);
        uint4 u1 = __ldg((const uint4*)(XL + (size_t)s1 * 128) + hl);
        for (int it = 1; it < nfull; it++) {
            int t0 = __ldg(&g_CSR[e + 4 + half]);
            int t1 = __ldg(&g_CSR[e + 6 + half]);
            uint4 v0 = __ldg((const uint4*)(XL + (size_t)t0 * 128) + hl);
            uint4 v1 = __ldg((const uint4*)(XL + (size_t)t1 * 128) + hl);
            AGG_STEP(u0, u1);
            u0 = v0; u1 = v1;
            e += 4;
        }
        AGG_STEP(u0, u1);
        e += 4;
    }
    // tail: up to 3 edges, 2 per step with validity masking
    for (; e < e1; e += 2) {
        int ei = e + half;
        bool valid = ei < e1;
        int src = __ldg(&g_CSR[valid ? ei : e]);
        uint4 u = __ldg((const uint4*)(XL + (size_t)src * 128) + hl);
        float4 xA, xB;
        unp16(u, xA, xB);
        float p = logit8(xA, xB, xrA, xrB, a6A, a4A, a6B, a4B);
        p += __shfl_xor_sync(0xFFFFFFFFu, p, 1);
        p += __shfl_xor_sync(0xFFFFFFFFu, p, 2);
        float w = valid ? __expf(p) : 0.f;
        s += w;
        accA.x += w * xA.x; accA.y += w * xA.y;
        accA.z += w * xA.z; accA.w += w * xA.w;
        accB.x += w * xB.x; accB.y += w * xB.y;
        accB.z += w * xB.z; accB.w += w * xB.w;
    }

    s += __shfl_xor_sync(0xFFFFFFFFu, s, 16);
    accA.x += __shfl_down_sync(0xFFFFFFFFu, accA.x, 16);
    accA.y += __shfl_down_sync(0xFFFFFFFFu, accA.y, 16);
    accA.z += __shfl_down_sync(0xFFFFFFFFu, accA.z, 16);
    accA.w += __shfl_down_sync(0xFFFFFFFFu, accA.w, 16);
    accB.x += __shfl_up_sync(0xFFFFFFFFu, accB.x, 16);
    accB.y += __shfl_up_sync(0xFFFFFFFFu, accB.y, 16);
    accB.z += __shfl_up_sync(0xFFFFFFFFu, accB.z, 16);
    accB.w += __shfl_up_sync(0xFFFFFFFFu, accB.w, 16);

    float inv = 1.f / (s + 1e-16f);
    float4 acc = half ? accB : accA;
    float4 b4 = __ldg((const float4*)bias + 2 * hl + half);
    float4 o;
    o.x = fmaxf(acc.x * inv + b4.x, 0.f);
    o.y = fmaxf(acc.y * inv + b4.y, 0.f);
    o.z = fmaxf(acc.z * inv + b4.z, 0.f);
    o.w = fmaxf(acc.w * inv + b4.w, 0.f);
    *((float4*)(out + (size_t)warp * 128) + 2 * hl + half) = o;
}

// ------------------------- launch --------------------------------------------
extern "C" void kernel_launch(void* const* d_in, const int* in_sizes, int n_in,
                              void* d_out, int out_size) {
    const float* x    = (const float*)d_in[0];
    const void*  ei   = d_in[1];
    const float* W1l  = (const float*)d_in[2];
    const float* W1r  = (const float*)d_in[3];
    const float* att1 = (const float*)d_in[4];
    const float* b1   = (const float*)d_in[5];
    const float* W2l  = (const float*)d_in[6];
    const float* W2r  = (const float*)d_in[7];
    const float* att2 = (const float*)d_in[8];
    const float* b2   = (const float*)d_in[9];
    float* out = (float*)d_out;

    __half *XL, *XR;
    float *H1;
    cudaGetSymbolAddress((void**)&XL, g_XLh);
    cudaGetSymbolAddress((void**)&XR, g_XRh);
    cudaGetSymbolAddress((void**)&H1, g_H1);

    static cudaStream_t s1 = nullptr;
    static cudaEvent_t evFork = nullptr, evG1 = nullptr;
    if (!s1) {
        cudaStreamCreateWithFlags(&s1, cudaStreamNonBlocking);
        cudaEventCreateWithFlags(&evFork, cudaEventDisableTiming);
        cudaEventCreateWithFlags(&evG1, cudaEventDisableTiming);
    }

    int gemm_grid = (N_NODES + 127) / 128;
    int agg_grid  = (N_NODES * 32 + 255) / 256;
    int nblk = (N_NODES + 1023) / 1024;
    int edge4_grid = (E_TOT / 4 + 255) / 256;

    // fork: layer-1 GEMM on side stream, concurrent with CSR build
    cudaEventRecord(evFork, 0);
    cudaStreamWaitEvent(s1, evFork, 0);
    k_gemm_tc<<<gemm_grid, 512, 0, s1>>>(x, W1l, W1r, XL, XR, N_NODES);
    cudaEventRecord(evG1, s1);

    // CSR build on main stream (3 kernels, 4 edges/thread)
    k_hist<<<edge4_grid, 256>>>(ei);
    k_scanf<<<nblk, 1024>>>();
    k_scatter<<<edge4_grid, 256>>>(ei);

    // join
    cudaStreamWaitEvent(0, evG1, 0);

    // layer 1 aggregate
    k_agg<<<agg_grid, 256>>>(XL, XR, att1, b1, H1);

    // layer 2
    k_gemm_tc<<<gemm_grid, 512>>>(H1, W2l, W2r, XL, XR, N_NODES);
    k_agg<<<agg_grid, 256>>>(XL, XR, att2, b2, out);
}